// round 1
// baseline (speedup 1.0000x reference)
#include <cuda_runtime.h>
#include <cuda_bf16.h>

// HeadWise_JSD: reference collapses to
//   out = (0.5/12) * sum_{b,h,l} p * (log p - log q)
// since m = log(0.5*(p+p)) == log(p) bit-exactly, making kl_pm == 0.
//
// Pure HBM-bound streaming reduction over 2 x 201 MB fp32. The log must NOT
// go through MUFU (2 LG2/elem = ~700us chip-wide at MUFU rt=8); use an
// FFMA-only cephes-style polynomial instead.

static __device__ __forceinline__ float fast_logf(float v) {
    // v in ~(4e-7, 1e-2] here: positive, normal. cephes logf.
    int   i  = __float_as_int(v);
    // frexp-style: mantissa in [0.5, 1), unbiased exponent e s.t. v = m * 2^e
    float fe = (float)(((i >> 23) & 0xff) - 126);
    float m  = __int_as_float((i & 0x007fffff) | 0x3f000000); // [0.5, 1)
    float x;
    if (m < 0.70710678118654752f) { fe -= 1.0f; x = m + m - 1.0f; }
    else                          {             x = m - 1.0f;     }
    float z = x * x;
    float y =            7.0376836292e-2f;
    y = fmaf(y, x, -1.1514610310e-1f);
    y = fmaf(y, x,  1.1676998740e-1f);
    y = fmaf(y, x, -1.2420140846e-1f);
    y = fmaf(y, x,  1.4249322787e-1f);
    y = fmaf(y, x, -1.6668057665e-1f);
    y = fmaf(y, x,  2.0000714765e-1f);
    y = fmaf(y, x, -2.4999993993e-1f);
    y = fmaf(y, x,  3.3333331174e-1f);
    y = y * x * z;
    y = fmaf(fe, -2.12194440e-4f, y);
    y = fmaf(-0.5f, z, y);
    x = x + y;
    x = fmaf(fe, 0.693359375f, x);
    return x;
}

static __device__ __forceinline__ float term(float p, float q) {
    return p * (fast_logf(p) - fast_logf(q));
}

__global__ void jsd_zero_kernel(float* out) {
    if (threadIdx.x == 0 && blockIdx.x == 0) out[0] = 0.0f;
}

__global__ __launch_bounds__(256) void jsd_reduce_kernel(
    const float4* __restrict__ p4,
    const float4* __restrict__ q4,
    float* __restrict__ out,
    long long n4)
{
    long long idx    = (long long)blockIdx.x * blockDim.x + threadIdx.x;
    long long stride = (long long)gridDim.x * blockDim.x;

    float acc = 0.0f;
    for (long long i = idx; i < n4; i += stride) {
        float4 pv = p4[i];
        float4 qv = q4[i];
        acc += term(pv.x, qv.x);
        acc += term(pv.y, qv.y);
        acc += term(pv.z, qv.z);
        acc += term(pv.w, qv.w);
    }

    // warp reduction
    #pragma unroll
    for (int o = 16; o; o >>= 1)
        acc += __shfl_xor_sync(0xffffffffu, acc, o);

    __shared__ float smem[8];  // 256 threads = 8 warps
    int lane = threadIdx.x & 31;
    int warp = threadIdx.x >> 5;
    if (lane == 0) smem[warp] = acc;
    __syncthreads();

    if (warp == 0) {
        float v = (lane < 8) ? smem[lane] : 0.0f;
        #pragma unroll
        for (int o = 4; o; o >>= 1)
            v += __shfl_xor_sync(0xffffffffu, v, o);
        if (lane == 0)
            atomicAdd(out, v * (0.5f / 12.0f));
    }
}

extern "C" void kernel_launch(void* const* d_in, const int* in_sizes, int n_in,
                              void* d_out, int out_size) {
    const float4* p4 = (const float4*)d_in[0];
    const float4* q4 = (const float4*)d_in[1];
    float* out = (float*)d_out;

    long long n  = (long long)in_sizes[0];   // 1024*12*4096, divisible by 4
    long long n4 = n >> 2;

    jsd_zero_kernel<<<1, 32>>>(out);

    const int threads = 256;
    const int blocks  = 148 * 8;   // ~41 float4 iters/thread: deep MLP, even waves
    jsd_reduce_kernel<<<blocks, threads>>>(p4, q4, out, n4);
}

// round 2
// speedup vs baseline: 1.3871x; 1.3871x over previous
#include <cuda_runtime.h>
#include <cuda_bf16.h>

// HeadWise_JSD: reference collapses to
//   out = (0.5/12) * sum_{b,h,l} p * (log p - log q)
// since m = log(0.5*(p+p)) == log(p) bit-exactly -> kl_pm == 0.
//
// Streaming reduction over 2 x 201 MB fp32 (~402 MB HBM traffic, floor ~57us).
// R1 was issue-bound (fma 50% / alu 57% / issue 84%, DRAM only 47%) due to a
// 2x17-instr polynomial log. Replace with MUFU.LG2 on the mantissa (exact
// integer exponent handling keeps accuracy ~1e-7):
//   log p - log q = ln2 * ( lg2(mant_p) - lg2(mant_q) + (exp_p - exp_q) )

static __device__ __forceinline__ float term(float p, float q) {
    int ip = __float_as_int(p);
    int iq = __float_as_int(q);
    // mantissa forced into [1,2): lg2 result in [0,1), tiny ulp error
    float mp = __int_as_float((ip & 0x007fffff) | 0x3f800000);
    float mq = __int_as_float((iq & 0x007fffff) | 0x3f800000);
    float lp = __log2f(mp);           // MUFU.LG2
    float lq = __log2f(mq);           // MUFU.LG2
    int   de = (ip >> 23) - (iq >> 23);   // exact exponent difference (both > 0)
    float l2 = (lp - lq) + (float)de;     // log2(p/q), exact exponent part
    return p * l2;                        // (xln2 folded in at the end)
}

__global__ void jsd_zero_kernel(float* out) {
    if (threadIdx.x == 0 && blockIdx.x == 0) out[0] = 0.0f;
}

__global__ __launch_bounds__(256) void jsd_reduce_kernel(
    const float4* __restrict__ p4,
    const float4* __restrict__ q4,
    float* __restrict__ out,
    long long n4)
{
    long long idx    = (long long)blockIdx.x * blockDim.x + threadIdx.x;
    long long stride = (long long)gridDim.x * blockDim.x;

    float acc = 0.0f;
    #pragma unroll 4
    for (long long i = idx; i < n4; i += stride) {
        float4 pv = p4[i];
        float4 qv = q4[i];
        acc += term(pv.x, qv.x);
        acc += term(pv.y, qv.y);
        acc += term(pv.z, qv.z);
        acc += term(pv.w, qv.w);
    }

    // fold ln2 once per thread (we accumulated log2-units)
    acc *= 0.69314718055994531f;

    // warp reduction
    #pragma unroll
    for (int o = 16; o; o >>= 1)
        acc += __shfl_xor_sync(0xffffffffu, acc, o);

    __shared__ float smem[8];  // 256 threads = 8 warps
    int lane = threadIdx.x & 31;
    int warp = threadIdx.x >> 5;
    if (lane == 0) smem[warp] = acc;
    __syncthreads();

    if (warp == 0) {
        float v = (lane < 8) ? smem[lane] : 0.0f;
        #pragma unroll
        for (int o = 4; o; o >>= 1)
            v += __shfl_xor_sync(0xffffffffu, v, o);
        if (lane == 0)
            atomicAdd(out, v * (0.5f / 12.0f));
    }
}

extern "C" void kernel_launch(void* const* d_in, const int* in_sizes, int n_in,
                              void* d_out, int out_size) {
    const float4* p4 = (const float4*)d_in[0];
    const float4* q4 = (const float4*)d_in[1];
    float* out = (float*)d_out;

    long long n  = (long long)in_sizes[0];   // 1024*12*4096, divisible by 4
    long long n4 = n >> 2;

    jsd_zero_kernel<<<1, 32>>>(out);

    const int threads = 256;
    const int blocks  = 148 * 8;
    jsd_reduce_kernel<<<blocks, threads>>>(p4, q4, out, n4);
}

// round 3
// speedup vs baseline: 1.5610x; 1.1254x over previous
#include <cuda_runtime.h>
#include <cuda_bf16.h>

// HeadWise_JSD: out = (0.5/12) * sum p * (log p - log q)   [kl_pm == 0 exactly]
// Streaming reduction over 2 x 201 MB fp32; HBM floor ~55-60us.
// R2 (73.8us): DRAM 64.5%, nothing saturated -> latency-exposed (MLP~2/thread,
// regs=36). R3: front-batch 8 LDG.128 per macro-iter (MLP_p1=8), int32 index,
// 4 independent accumulators.

static __device__ __forceinline__ float term(float p, float q) {
    int ip = __float_as_int(p);
    int iq = __float_as_int(q);
    float mp = __int_as_float((ip & 0x007fffff) | 0x3f800000); // [1,2)
    float mq = __int_as_float((iq & 0x007fffff) | 0x3f800000);
    float lp = __log2f(mp);            // MUFU.LG2, arg in [1,2): tiny ulp err
    float lq = __log2f(mq);
    int   de = (ip >> 23) - (iq >> 23);    // exact exponent diff (p,q > 0)
    return p * ((lp - lq) + (float)de);    // log2-units; ln2 folded at end
}

static __device__ __forceinline__ float term4(float4 pv, float4 qv) {
    float a = term(pv.x, qv.x) + term(pv.y, qv.y);
    float b = term(pv.z, qv.z) + term(pv.w, qv.w);
    return a + b;
}

__global__ void jsd_zero_kernel(float* out) {
    if (threadIdx.x == 0 && blockIdx.x == 0) out[0] = 0.0f;
}

__global__ __launch_bounds__(256) void jsd_reduce_kernel(
    const float4* __restrict__ p4,
    const float4* __restrict__ q4,
    float* __restrict__ out,
    int n4)
{
    const int stride = gridDim.x * 256;
    int i = blockIdx.x * 256 + threadIdx.x;

    float a0 = 0.0f, a1 = 0.0f, a2 = 0.0f, a3 = 0.0f;

    // main loop: 8 front-batched LDG.128 per macro-iter (deep MLP)
    for (; i + 3 * stride < n4; i += 4 * stride) {
        float4 p0 = p4[i];
        float4 p1 = p4[i + stride];
        float4 p2 = p4[i + 2 * stride];
        float4 p3 = p4[i + 3 * stride];
        float4 q0 = q4[i];
        float4 q1 = q4[i + stride];
        float4 q2 = q4[i + 2 * stride];
        float4 q3 = q4[i + 3 * stride];
        a0 += term4(p0, q0);
        a1 += term4(p1, q1);
        a2 += term4(p2, q2);
        a3 += term4(p3, q3);
    }
    // tail (empty when n4 % (4*stride*?) aligns; kept for safety)
    for (; i < n4; i += stride)
        a0 += term4(p4[i], q4[i]);

    float acc = ((a0 + a1) + (a2 + a3)) * 0.69314718055994531f; // ln2

    #pragma unroll
    for (int o = 16; o; o >>= 1)
        acc += __shfl_xor_sync(0xffffffffu, acc, o);

    __shared__ float smem[8];
    int lane = threadIdx.x & 31;
    int warp = threadIdx.x >> 5;
    if (lane == 0) smem[warp] = acc;
    __syncthreads();

    if (warp == 0) {
        float v = (lane < 8) ? smem[lane] : 0.0f;
        #pragma unroll
        for (int o = 4; o; o >>= 1)
            v += __shfl_xor_sync(0xffffffffu, v, o);
        if (lane == 0)
            atomicAdd(out, v * (0.5f / 12.0f));
    }
}

extern "C" void kernel_launch(void* const* d_in, const int* in_sizes, int n_in,
                              void* d_out, int out_size) {
    const float4* p4 = (const float4*)d_in[0];
    const float4* q4 = (const float4*)d_in[1];
    float* out = (float*)d_out;

    int n  = in_sizes[0];     // 1024*12*4096
    int n4 = n >> 2;          // 12,582,912 float4 pairs

    jsd_zero_kernel<<<1, 32>>>(out);

    // 1536 blocks * 256 thr = 393216 threads -> exactly 32 float4/thread
    const int threads = 256;
    const int blocks  = 1536;
    jsd_reduce_kernel<<<blocks, threads>>>(p4, q4, out, n4);
}

// round 4
// speedup vs baseline: 1.5625x; 1.0010x over previous
#include <cuda_runtime.h>
#include <cuda_bf16.h>

// HeadWise_JSD: out = (0.5/12) * sum p * (log p - log q)   [kl_pm == 0 exactly]
// Streaming reduction over 2 x 201 MB fp32; HBM floor ~55us @ achieved peak.
// R3 (65.6us, DRAM 77.5%): 1536 blocks @ ~6 blocks/SM = 1.73 waves (tail
// imbalance) and regs=38 clipped the 8-deep load batch. R4: single full wave
// (592 blocks, launch_bounds(256,4) -> 64-reg budget), __ldcs streaming loads.

static __device__ __forceinline__ float term(float p, float q) {
    int ip = __float_as_int(p);
    int iq = __float_as_int(q);
    float mp = __int_as_float((ip & 0x007fffff) | 0x3f800000); // [1,2)
    float mq = __int_as_float((iq & 0x007fffff) | 0x3f800000);
    float lp = __log2f(mp);            // MUFU.LG2, arg in [1,2): tiny ulp err
    float lq = __log2f(mq);
    int   de = (ip >> 23) - (iq >> 23);    // exact exponent diff (p,q > 0)
    return p * ((lp - lq) + (float)de);    // log2-units; ln2 folded at end
}

static __device__ __forceinline__ float term4(float4 pv, float4 qv) {
    float a = term(pv.x, qv.x) + term(pv.y, qv.y);
    float b = term(pv.z, qv.z) + term(pv.w, qv.w);
    return a + b;
}

__global__ void jsd_zero_kernel(float* out) {
    if (threadIdx.x == 0 && blockIdx.x == 0) out[0] = 0.0f;
}

__global__ __launch_bounds__(256, 4) void jsd_reduce_kernel(
    const float4* __restrict__ p4,
    const float4* __restrict__ q4,
    float* __restrict__ out,
    int n4)
{
    const int stride = gridDim.x * 256;
    int i = blockIdx.x * 256 + threadIdx.x;

    float a0 = 0.0f, a1 = 0.0f, a2 = 0.0f, a3 = 0.0f;

    // 8 front-batched streaming LDG.128.CS per macro-iter (deep MLP)
    for (; i + 3 * stride < n4; i += 4 * stride) {
        float4 p0 = __ldcs(p4 + i);
        float4 p1 = __ldcs(p4 + i + stride);
        float4 p2 = __ldcs(p4 + i + 2 * stride);
        float4 p3 = __ldcs(p4 + i + 3 * stride);
        float4 q0 = __ldcs(q4 + i);
        float4 q1 = __ldcs(q4 + i + stride);
        float4 q2 = __ldcs(q4 + i + 2 * stride);
        float4 q3 = __ldcs(q4 + i + 3 * stride);
        a0 += term4(p0, q0);
        a1 += term4(p1, q1);
        a2 += term4(p2, q2);
        a3 += term4(p3, q3);
    }
    for (; i < n4; i += stride)
        a0 += term4(__ldcs(p4 + i), __ldcs(q4 + i));

    float acc = ((a0 + a1) + (a2 + a3)) * 0.69314718055994531f; // ln2

    #pragma unroll
    for (int o = 16; o; o >>= 1)
        acc += __shfl_xor_sync(0xffffffffu, acc, o);

    __shared__ float smem[8];
    int lane = threadIdx.x & 31;
    int warp = threadIdx.x >> 5;
    if (lane == 0) smem[warp] = acc;
    __syncthreads();

    if (warp == 0) {
        float v = (lane < 8) ? smem[lane] : 0.0f;
        #pragma unroll
        for (int o = 4; o; o >>= 1)
            v += __shfl_xor_sync(0xffffffffu, v, o);
        if (lane == 0)
            atomicAdd(out, v * (0.5f / 12.0f));
    }
}

extern "C" void kernel_launch(void* const* d_in, const int* in_sizes, int n_in,
                              void* d_out, int out_size) {
    const float4* p4 = (const float4*)d_in[0];
    const float4* q4 = (const float4*)d_in[1];
    float* out = (float*)d_out;

    int n  = in_sizes[0];     // 1024*12*4096
    int n4 = n >> 2;          // 12,582,912 float4 pairs

    jsd_zero_kernel<<<1, 32>>>(out);

    // 148 SMs x 4 blocks = 592 blocks: exactly one wave at 4 blocks/SM
    const int threads = 256;
    const int blocks  = 592;
    jsd_reduce_kernel<<<blocks, threads>>>(p4, q4, out, n4);
}